// round 5
// baseline (speedup 1.0000x reference)
#include <cuda_runtime.h>
#include <cstdint>

// Graph unpooling: out[dst] += edge_attr * x[src]
//   x [50000,128] f32, src/dst [E=800000] i32, edge_attr [E] f32, out [200000,128] f32
// Strategy: per-call dst-CSR (hist -> single-pass lookback scan -> fill),
// then warp-per-node register accumulation with one streaming store.

#define MAXN   200704
#define MAXE   800000
#define SCAN_B 1024
#define NBLK_MAX 256

__device__ int  g_count[MAXN];     // per-node edge count
__device__ int2 g_meta[MAXN];      // {segment start, count}
__device__ int  g_cursor[MAXN];    // running fill position
__device__ int2 g_edges[MAXE];     // CSR payload: {src, bitcast(weight)}

// decoupled-lookback state
__device__ int           g_ticket;
__device__ volatile int  g_flag[NBLK_MAX];     // 0=invalid 1=aggregate 2=prefix
__device__ volatile int  g_aggr[NBLK_MAX];
__device__ volatile int  g_pfx[NBLK_MAX];

__global__ void k_reset(int n, int nb) {
    int i = blockIdx.x * blockDim.x + threadIdx.x;
    if (i < n) g_count[i] = 0;
    if (i < nb) g_flag[i] = 0;
    if (i == 0) g_ticket = 0;
}

__global__ void k_hist(const int* __restrict__ dst, int E) {
    int e = blockIdx.x * blockDim.x + threadIdx.x;
    if (e < E) atomicAdd(&g_count[dst[e]], 1);
}

// Single-pass scan with decoupled lookback. Atomic ticket guarantees blocks
// acquire ids in scheduling order -> lookback spins only on resident blocks.
__global__ void __launch_bounds__(SCAN_B)
k_scan(int n) {
    __shared__ int swarp[32];
    __shared__ int sbid, sbase;
    int t = threadIdx.x, lane = t & 31, wid = t >> 5;

    if (t == 0) sbid = atomicAdd(&g_ticket, 1);
    __syncthreads();
    int bid = sbid;
    int i = bid * SCAN_B + t;
    int c = (i < n) ? g_count[i] : 0;

    // block inclusive scan via shfl
    int v = c;
    #pragma unroll
    for (int off = 1; off < 32; off <<= 1) {
        int u = __shfl_up_sync(0xffffffffu, v, off);
        if (lane >= off) v += u;
    }
    if (lane == 31) swarp[wid] = v;
    __syncthreads();
    if (wid == 0) {
        int w = swarp[lane];
        #pragma unroll
        for (int off = 1; off < 32; off <<= 1) {
            int u = __shfl_up_sync(0xffffffffu, w, off);
            if (lane >= off) w += u;
        }
        swarp[lane] = w;
    }
    __syncthreads();
    int incl = v + (wid > 0 ? swarp[wid - 1] : 0);
    int total = swarp[31];

    // lookback (thread 0)
    if (t == 0) {
        if (bid == 0) {
            g_pfx[0] = total; __threadfence(); g_flag[0] = 2;
            sbase = 0;
        } else {
            g_aggr[bid] = total; __threadfence(); g_flag[bid] = 1;
            int base = 0;
            for (int j = bid - 1; j >= 0; j--) {
                int f;
                while ((f = g_flag[j]) == 0) { }
                if (f == 2) { base += g_pfx[j]; break; }
                base += g_aggr[j];
            }
            g_pfx[bid] = base + total; __threadfence(); g_flag[bid] = 2;
            sbase = base;
        }
    }
    __syncthreads();

    if (i < n) {
        int st = sbase + incl - c;
        g_meta[i]   = make_int2(st, c);
        g_cursor[i] = st;
    }
}

__global__ void k_fill(const int* __restrict__ src, const int* __restrict__ dst,
                       const float* __restrict__ attr, int E) {
    int e = blockIdx.x * blockDim.x + threadIdx.x;
    if (e >= E) return;
    int pos = atomicAdd(&g_cursor[dst[e]], 1);
    g_edges[pos] = make_int2(src[e], __float_as_int(attr[e]));
}

// One warp per fine node: 4-deep load pipeline, register accumulate,
// single streaming store (keeps x resident in L2).
__global__ void __launch_bounds__(256)
k_gather(const float4* __restrict__ x4, float4* __restrict__ out4, int n) {
    int gtid = blockIdx.x * blockDim.x + threadIdx.x;
    int node = gtid >> 5;
    int lane = gtid & 31;
    if (node >= n) return;

    int2 mc  = __ldg(&g_meta[node]);
    int  beg = mc.x, cnt = mc.y;

    float4 a0 = make_float4(0.f, 0.f, 0.f, 0.f);
    float4 a1 = make_float4(0.f, 0.f, 0.f, 0.f);
    int k = 0;
    for (; k + 3 < cnt; k += 4) {
        int2 e0 = __ldg(&g_edges[beg + k]);
        int2 e1 = __ldg(&g_edges[beg + k + 1]);
        int2 e2 = __ldg(&g_edges[beg + k + 2]);
        int2 e3 = __ldg(&g_edges[beg + k + 3]);
        float4 v0 = __ldg(&x4[(size_t)e0.x * 32 + lane]);
        float4 v1 = __ldg(&x4[(size_t)e1.x * 32 + lane]);
        float4 v2 = __ldg(&x4[(size_t)e2.x * 32 + lane]);
        float4 v3 = __ldg(&x4[(size_t)e3.x * 32 + lane]);
        float w0 = __int_as_float(e0.y), w1 = __int_as_float(e1.y);
        float w2 = __int_as_float(e2.y), w3 = __int_as_float(e3.y);
        a0.x += w0 * v0.x; a0.y += w0 * v0.y; a0.z += w0 * v0.z; a0.w += w0 * v0.w;
        a1.x += w1 * v1.x; a1.y += w1 * v1.y; a1.z += w1 * v1.z; a1.w += w1 * v1.w;
        a0.x += w2 * v2.x; a0.y += w2 * v2.y; a0.z += w2 * v2.z; a0.w += w2 * v2.w;
        a1.x += w3 * v3.x; a1.y += w3 * v3.y; a1.z += w3 * v3.z; a1.w += w3 * v3.w;
    }
    if (k + 1 < cnt) {
        int2 e0 = __ldg(&g_edges[beg + k]);
        int2 e1 = __ldg(&g_edges[beg + k + 1]);
        float4 v0 = __ldg(&x4[(size_t)e0.x * 32 + lane]);
        float4 v1 = __ldg(&x4[(size_t)e1.x * 32 + lane]);
        float w0 = __int_as_float(e0.y), w1 = __int_as_float(e1.y);
        a0.x += w0 * v0.x; a0.y += w0 * v0.y; a0.z += w0 * v0.z; a0.w += w0 * v0.w;
        a1.x += w1 * v1.x; a1.y += w1 * v1.y; a1.z += w1 * v1.z; a1.w += w1 * v1.w;
        k += 2;
    }
    if (k < cnt) {
        int2 e0 = __ldg(&g_edges[beg + k]);
        float4 v0 = __ldg(&x4[(size_t)e0.x * 32 + lane]);
        float w0 = __int_as_float(e0.y);
        a0.x += w0 * v0.x; a0.y += w0 * v0.y; a0.z += w0 * v0.z; a0.w += w0 * v0.w;
    }
    a0.x += a1.x; a0.y += a1.y; a0.z += a1.z; a0.w += a1.w;
    __stcs(&out4[(size_t)node * 32 + lane], a0);
}

extern "C" void kernel_launch(void* const* d_in, const int* in_sizes, int n_in,
                              void* d_out, int out_size) {
    const float4* x4   = (const float4*)d_in[0];
    const int*    src  = (const int*)d_in[1];
    const int*    dst  = (const int*)d_in[2];
    const float*  attr = (const float*)d_in[3];
    float4*       out4 = (float4*)d_out;

    int E  = in_sizes[1];
    int n  = out_size / 128;                 // fine nodes (C=128)
    int nb = (n + SCAN_B - 1) / SCAN_B;      // scan blocks (<= NBLK_MAX)

    int tb = 256;
    k_reset<<<(n + tb - 1) / tb, tb>>>(n, nb);
    k_hist <<<(E + tb - 1) / tb, tb>>>(dst, E);
    k_scan <<<nb, SCAN_B>>>(n);
    k_fill <<<(E + tb - 1) / tb, tb>>>(src, dst, attr, E);

    long long gt = (long long)n * 32;
    k_gather<<<(int)((gt + tb - 1) / tb), tb>>>(x4, out4, n);
}